// round 6
// baseline (speedup 1.0000x reference)
#include <cuda_runtime.h>

#define H    16
#define NBOX 128
#define DIN  256
#define DKD  128
#define DG   64

typedef unsigned long long ull;

// Scratch (device globals — no allocations allowed)
__device__ float g_glog[H * NBOX * NBOX];      // log(clip(relu(gate))): 1 MB
__device__ float g_qkv[3 * H * NBOX * DKD];    // k,q,v projections: 3 MB
__device__ float g_partial[H * 4 * DKD];       // per-mtile partial colsums

// ---- packed f32x2 helpers (sm_10x FFMA2) ----------------------------------
__device__ __forceinline__ void fma2(ull& acc, ull a, ull b) {
    asm("fma.rn.f32x2 %0, %1, %2, %0;" : "+l"(acc) : "l"(a), "l"(b));
}
__device__ __forceinline__ ull dup2(float a) {
    ull r; asm("mov.b64 %0, {%1, %1};" : "=l"(r) : "f"(a)); return r;
}
__device__ __forceinline__ float2 unpack2(ull v) {
    float2 r; asm("mov.b64 {%0, %1}, %2;" : "=f"(r.x), "=f"(r.y) : "l"(v)); return r;
}

// ---------------------------------------------------------------------------
// k_front (256 threads, 448 blocks):
//   blocks [0,192): proj tile 128x32: C = f_a(128x256) @ W[h,p][:, 32ct..] + b
//     * W slice (32 KB) burst-loaded to smem ONCE at block start: all of W's
//       6 MB DRAM traffic is front-loaded chip-wide with huge MLP.
//     * f_a streamed from L2 (hot, shared by all blocks) in 16-d chunks with
//       register prefetch issued before compute -> latency hidden.
//     * inner loop: A warp-uniform LDS.128 (row pairs), B per-lane LDS.32,
//       8 FFMA2 per d per thread.
//   blocks [192,448): gate: glog[h,m,n] = log(max(pos[m,n,:]·WG[h]+bg[h],1e-6))
// ---------------------------------------------------------------------------
__global__ void __launch_bounds__(256) k_front(
        const float* __restrict__ f_a,
        const float* __restrict__ pos,
        const float* __restrict__ WG, const float* __restrict__ bg,
        const float* __restrict__ WK, const float* __restrict__ bk,
        const float* __restrict__ WQ, const float* __restrict__ bq,
        const float* __restrict__ WV, const float* __restrict__ bv) {
    __shared__ __align__(16) char smem_raw[46080];  // proj 45312 / gate 20736
    int tid = threadIdx.x;

    if (blockIdx.x < 192) {
        // ---------------- proj path ----------------
        // Ws[d][c]:  W slice, 256 x 36 pad (36864 B)
        // AsT[d][r]: f_a chunk transposed, 16 x 132 pad (8448 B)
        float (*Ws)[36]   = (float(*)[36])smem_raw;
        float (*AsT)[132] = (float(*)[132])(smem_raw + 36864);

        int bid = blockIdx.x;
        int ct = bid & 3;              // column tile: cols 32ct .. 32ct+31
        int p  = (bid >> 2) % 3;
        int h  = bid / 12;
        const float* W  = (p == 0) ? WK : ((p == 1) ? WQ : WV);
        const float* bb = (p == 0) ? bk : ((p == 1) ? bq : bv);
        const float* Wh = W + (long)h * DIN * DKD;
        int c0 = 32 * ct;

        int w = tid >> 5, L = tid & 31;
        int r0 = 16 * w;               // warp rows r0 .. r0+15

        float4 pa[2];

#define LOADA(KK)                                                              \
        {                                                                      \
            _Pragma("unroll")                                                  \
            for (int it = 0; it < 2; ++it) {                                   \
                int fidx = tid + 256 * it;                                     \
                int r = fidx >> 2, q = fidx & 3;                               \
                pa[it] = *(const float4*)&f_a[r * DIN + (KK) + 4 * q];         \
            }                                                                  \
        }
#define STSA()                                                                 \
        {                                                                      \
            _Pragma("unroll")                                                  \
            for (int it = 0; it < 2; ++it) {                                   \
                int fidx = tid + 256 * it;                                     \
                int r = fidx >> 2, q = fidx & 3;                               \
                AsT[4 * q + 0][r] = pa[it].x;                                  \
                AsT[4 * q + 1][r] = pa[it].y;                                  \
                AsT[4 * q + 2][r] = pa[it].z;                                  \
                AsT[4 * q + 3][r] = pa[it].w;                                  \
            }                                                                  \
        }

        // Prologue: prefetch A chunk 0, burst-load full W slice (32 KB).
        LOADA(0);
#pragma unroll
        for (int it = 0; it < 8; ++it) {
            int fidx = tid + 256 * it;               // 0..2047
            int d = fidx >> 3, c4 = fidx & 7;        // 256 d x 8 float4
            float4 v = *(const float4*)&Wh[d * DKD + c0 + 4 * c4];
            *(float4*)&Ws[d][4 * c4] = v;
        }
        STSA();
        __syncthreads();

        ull acc[8] = {};   // acc[j] = out rows (r0+2j, r0+2j+1) @ col c0+L

        for (int c = 0; c < 16; ++c) {
            if (c < 15) LOADA(16 * (c + 1));         // issue early; hidden by compute
            int dg = 16 * c;
#pragma unroll 4
            for (int d = 0; d < 16; ++d) {
                ulonglong2 au0 = *(ulonglong2*)&AsT[d][r0 + 0];
                ulonglong2 au1 = *(ulonglong2*)&AsT[d][r0 + 4];
                ulonglong2 au2 = *(ulonglong2*)&AsT[d][r0 + 8];
                ulonglong2 au3 = *(ulonglong2*)&AsT[d][r0 + 12];
                ull b = dup2(Ws[dg + d][L]);
                fma2(acc[0], au0.x, b);
                fma2(acc[1], au0.y, b);
                fma2(acc[2], au1.x, b);
                fma2(acc[3], au1.y, b);
                fma2(acc[4], au2.x, b);
                fma2(acc[5], au2.y, b);
                fma2(acc[6], au3.x, b);
                fma2(acc[7], au3.y, b);
            }
            __syncthreads();
            if (c < 15) {
                STSA();
                __syncthreads();
            }
        }
#undef LOADA
#undef STSA

        float* outp = g_qkv + (long)(p * H + h) * NBOX * DKD;
        float bias = bb[h * DKD + c0 + L];
#pragma unroll
        for (int j = 0; j < 8; ++j) {
            float2 v = unpack2(acc[j]);
            int row = r0 + 2 * j;
            outp[(row + 0) * DKD + c0 + L] = v.x + bias;
            outp[(row + 1) * DKD + c0 + L] = v.y + bias;
        }
    } else {
        // ---------------- gate path ----------------
        float (*pos_s)[65] = (float(*)[65])smem_raw;             // 64x65 = 16640 B
        float* wg_s = (float*)(smem_raw + 64 * 65 * 4);          // 16x64 =  4096 B

        int p0 = (blockIdx.x - 192) * 64;   // pair base (pair = m*128+n)

        ((float4*)wg_s)[tid] = ((const float4*)WG)[tid];
#pragma unroll
        for (int it = 0; it < 4; ++it) {
            int fidx = tid + 256 * it;
            int pl = fidx >> 4, g4 = fidx & 15;
            float4 v = ((const float4*)pos)[(long)(p0 + pl) * 16 + g4];
            pos_s[pl][4 * g4 + 0] = v.x;
            pos_s[pl][4 * g4 + 1] = v.y;
            pos_s[pl][4 * g4 + 2] = v.z;
            pos_s[pl][4 * g4 + 3] = v.w;
        }
        __syncthreads();

        int row = tid & 63;
        int hg  = tid >> 6;       // heads {hg, hg+4, hg+8, hg+12}
        float acc[4] = {0.f, 0.f, 0.f, 0.f};
#pragma unroll
        for (int g = 0; g < DG; ++g) {
            float pv = pos_s[row][g];
#pragma unroll
            for (int j = 0; j < 4; ++j)
                acc[j] = fmaf(pv, wg_s[(hg + 4 * j) * DG + g], acc[j]);
        }
#pragma unroll
        for (int j = 0; j < 4; ++j) {
            int h = hg + 4 * j;
            float x = acc[j] + bg[h];
            g_glog[h * (NBOX * NBOX) + p0 + row] = __logf(fmaxf(x, 1e-6f));
        }
    }
}

// ---------------------------------------------------------------------------
// k_attn: 32x128 score tile (f32x2 FMA), + glog, row softmax, partial colsums.
// grid (4, 16), 256 threads.
// ---------------------------------------------------------------------------
__global__ void k_attn() {
    __shared__ __align__(16) ull As2[32][33];
    __shared__ __align__(16) float Bs[32][132];
    __shared__ float psum[8][128];

    int tid = threadIdx.x;
    int mt = blockIdx.x, h = blockIdx.y;
    int m0 = mt * 32;
    int rg = tid >> 5;
    int cg = tid & 31;

    const float* kmat = g_qkv + (long)(0 * H + h) * NBOX * DKD;
    const float* qmat = g_qkv + (long)(1 * H + h) * NBOX * DKD;

    ull acc[4][2] = {};

    for (int kk = 0; kk < DKD; kk += 32) {
        {
            int r = tid >> 3, c4 = tid & 7;
            float4 v = *(const float4*)&kmat[(m0 + r) * DKD + kk + 4 * c4];
            As2[r][4 * c4 + 0] = dup2(v.x);
            As2[r][4 * c4 + 1] = dup2(v.y);
            As2[r][4 * c4 + 2] = dup2(v.z);
            As2[r][4 * c4 + 3] = dup2(v.w);
        }
#pragma unroll
        for (int it = 0; it < 4; ++it) {
            int fidx = tid + 256 * it;
            int n = fidx >> 3, c4 = fidx & 7;
            float4 v = *(const float4*)&qmat[n * DKD + kk + 4 * c4];
            Bs[4 * c4 + 0][n] = v.x;
            Bs[4 * c4 + 1][n] = v.y;
            Bs[4 * c4 + 2][n] = v.z;
            Bs[4 * c4 + 3][n] = v.w;
        }
        __syncthreads();

#pragma unroll
        for (int d = 0; d < 32; ++d) {
            ulonglong2 b = *(ulonglong2*)&Bs[d][4 * cg];
#pragma unroll
            for (int i = 0; i < 4; ++i) {
                ull a = As2[4 * rg + i][d];
                fma2(acc[i][0], a, b.x);
                fma2(acc[i][1], a, b.y);
            }
        }
        __syncthreads();
    }

    const float scale = 0.08838834764831843f;  // 1/sqrt(128)
    float csum[4] = {0.f, 0.f, 0.f, 0.f};
#pragma unroll
    for (int i = 0; i < 4; ++i) {
        int m = m0 + 4 * rg + i;
        float4 gl = *(const float4*)&g_glog[((long)h * NBOX + m) * NBOX + 4 * cg];
        float2 s0 = unpack2(acc[i][0]);
        float2 s1 = unpack2(acc[i][1]);
        float l[4];
        l[0] = s0.x * scale + gl.x;
        l[1] = s0.y * scale + gl.y;
        l[2] = s1.x * scale + gl.z;
        l[3] = s1.y * scale + gl.w;

        float mx = fmaxf(fmaxf(l[0], l[1]), fmaxf(l[2], l[3]));
#pragma unroll
        for (int off = 16; off; off >>= 1)
            mx = fmaxf(mx, __shfl_xor_sync(0xffffffffu, mx, off));

        float e[4], s = 0.f;
#pragma unroll
        for (int j = 0; j < 4; ++j) { e[j] = __expf(l[j] - mx); s += e[j]; }
#pragma unroll
        for (int off = 16; off; off >>= 1)
            s += __shfl_xor_sync(0xffffffffu, s, off);

        float rinv = 1.0f / s;
#pragma unroll
        for (int j = 0; j < 4; ++j) csum[j] += e[j] * rinv;
    }

#pragma unroll
    for (int j = 0; j < 4; ++j) psum[rg][4 * cg + j] = csum[j];
    __syncthreads();

    if (tid < 128) {
        float s = 0.f;
#pragma unroll
        for (int ww = 0; ww < 8; ++ww) s += psum[ww][tid];
        g_partial[(h * 4 + mt) * DKD + tid] = s;
    }
}

// ---------------------------------------------------------------------------
// k_out: out[i, c, d] = v[h,i,k]*colsum[h,k] + f_a[i,d]   (c = h*128+k)
// colsum computed inline from 4 partials. 16.7M float4 streaming stores.
// ---------------------------------------------------------------------------
__global__ void k_out(const float* __restrict__ f_a, float4* __restrict__ out) {
    int idx = blockIdx.x * 512 + threadIdx.x;   // 0..2^24-1
    int d4 = idx & 63;
    int c  = (idx >> 6) & 2047;
    int i  = idx >> 17;
    int h  = c >> 7;
    int k  = c & 127;

    float cs = g_partial[(h * 4 + 0) * DKD + k]
             + g_partial[(h * 4 + 1) * DKD + k]
             + g_partial[(h * 4 + 2) * DKD + k]
             + g_partial[(h * 4 + 3) * DKD + k];
    float s = g_qkv[((long)(2 * H + h) * NBOX + i) * DKD + k] * cs;
    float4 f = ((const float4*)f_a)[i * 64 + d4];
    __stcs(&out[idx], make_float4(s + f.x, s + f.y, s + f.z, s + f.w));
}

// ---------------------------------------------------------------------------
extern "C" void kernel_launch(void* const* d_in, const int* in_sizes, int n_in,
                              void* d_out, int out_size) {
    const float* f_a = (const float*)d_in[0];
    const float* pos = (const float*)d_in[1];
    const float* WG  = (const float*)d_in[2];
    const float* bg  = (const float*)d_in[3];
    const float* WK  = (const float*)d_in[4];
    const float* bk  = (const float*)d_in[5];
    const float* WQ  = (const float*)d_in[6];
    const float* bq  = (const float*)d_in[7];
    const float* WV  = (const float*)d_in[8];
    const float* bv  = (const float*)d_in[9];

    k_front<<<448, 256>>>(f_a, pos, WG, bg, WK, bk, WQ, bq, WV, bv);
    k_attn<<<dim3(4, 16), 256>>>();
    k_out<<<32768, 512>>>(f_a, (float4*)d_out);
}

// round 8
// speedup vs baseline: 1.1111x; 1.1111x over previous
#include <cuda_runtime.h>

#define H    16
#define NBOX 128
#define DIN  256
#define DKD  128
#define DG   64

typedef unsigned long long ull;

// Scratch (device globals — no allocations allowed)
__device__ float g_glog[H * NBOX * NBOX];      // log(clip(relu(gate))): 1 MB
__device__ float g_qkv[3 * H * NBOX * DKD];    // k,q,v projections: 3 MB
__device__ float g_partial[H * 4 * DKD];       // per-mtile partial colsums

// ---- packed f32x2 helpers (sm_10x FFMA2) ----------------------------------
__device__ __forceinline__ void fma2(ull& acc, ull a, ull b) {
    asm("fma.rn.f32x2 %0, %1, %2, %0;" : "+l"(acc) : "l"(a), "l"(b));
}
__device__ __forceinline__ ull dup2(float a) {
    ull r; asm("mov.b64 %0, {%1, %1};" : "=l"(r) : "f"(a)); return r;
}
__device__ __forceinline__ float2 unpack2(ull v) {
    float2 r; asm("mov.b64 {%0, %1}, %2;" : "=f"(r.x), "=f"(r.y) : "l"(v)); return r;
}

// Dynamic smem layout (proj): AsR 64x257 f32 (65792 B) | Ws2 256x66 ull (135168 B)
#define DS_A_PAD   257
#define DS_W_PAD   66
#define DS_TOTAL   (64 * DS_A_PAD * 4 + 256 * DS_W_PAD * 8)   // 200960

// ---------------------------------------------------------------------------
// k_front (256 threads, 352 blocks, 200 KB dynamic smem, 1 block/SM):
//   blocks [0,96): proj tile 64x128 for (h,p,mtile): C = A(64x256) @ W(256x128)
//     * A and the FULL W panel staged to smem ONCE; exactly ONE __syncthreads;
//       the 256-d compute loop has NO barriers and NO global loads.
//     * warp = 64 rows x 16 cols; thread = rows {2L,2L+1} x cols 16w..16w+15.
//       Per d: 2 per-lane LDS.32 (A, 2-way), 4 uniform LDS.128 (W), 16 FFMA2.
//   blocks [96,352): gate: glog[h,m,n] = log(max(pos[m,n,:]·WG[h]+bg[h],1e-6))
// ---------------------------------------------------------------------------
__global__ void __launch_bounds__(256) k_front(
        const float* __restrict__ f_a,
        const float* __restrict__ pos,
        const float* __restrict__ WG, const float* __restrict__ bg,
        const float* __restrict__ WK, const float* __restrict__ bk,
        const float* __restrict__ WQ, const float* __restrict__ bq,
        const float* __restrict__ WV, const float* __restrict__ bv) {
    extern __shared__ __align__(16) char dsm[];
    int tid = threadIdx.x;

    if (blockIdx.x < 96) {
        // ---------------- proj path ----------------
        float (*AsR)[DS_A_PAD] = (float(*)[DS_A_PAD])dsm;
        ull   (*Ws2)[DS_W_PAD] = (ull(*)[DS_W_PAD])(dsm + 64 * DS_A_PAD * 4);

        int bid = blockIdx.x;
        int mt = bid & 1;
        int p  = (bid >> 1) % 3;
        int h  = bid / 6;
        const float* W  = (p == 0) ? WK : ((p == 1) ? WQ : WV);
        const float* bb = (p == 0) ? bk : ((p == 1) ? bq : bv);
        const float* Wh = W + (long)h * DIN * DKD;
        int m0 = mt * 64;

        int w = tid >> 5, L = tid & 31;
        int cp0 = 8 * w;                  // warp col-pairs 8w..8w+7 (cols 16w..16w+15)
        int ra = 2 * L, rb = 2 * L + 1;   // this thread's two rows

        // ---- stage A: 64x256, coalesced LDG.128, scalar STS (pad-257 rows) ----
#pragma unroll
        for (int it = 0; it < 16; ++it) {
            int fidx = tid + 256 * it;
            int r = fidx >> 6, c4 = fidx & 63;
            float4 v = *(const float4*)&f_a[(m0 + r) * DIN + 4 * c4];
            AsR[r][4 * c4 + 0] = v.x;
            AsR[r][4 * c4 + 1] = v.y;
            AsR[r][4 * c4 + 2] = v.z;
            AsR[r][4 * c4 + 3] = v.w;
        }
        // ---- stage W: FULL 256x128 panel as f32x2 col-pairs ----
        // 8192 ulonglong2 total: 32 iterations x 256 threads.
        // fidx -> d = fidx>>5 (0..255), q = fidx&31; floats [4q,4q+4) of row d.
#pragma unroll
        for (int it = 0; it < 32; ++it) {
            int fidx = tid + 256 * it;
            int d = fidx >> 5, q = fidx & 31;
            ulonglong2 v = *(const ulonglong2*)&Wh[d * DKD + 4 * q];
            *(ulonglong2*)&Ws2[d][2 * q] = v;    // col-pairs 2q, 2q+1
        }
        __syncthreads();   // the ONLY barrier

        ull acc[2][8] = {};   // [row i][col-pair q]

        // software-pipelined main loop: zero barriers, zero global loads
        float a0 = AsR[ra][0], a1 = AsR[rb][0];
        ulonglong2 w0 = *(ulonglong2*)&Ws2[0][cp0 + 0];
        ulonglong2 w1 = *(ulonglong2*)&Ws2[0][cp0 + 2];
        ulonglong2 w2 = *(ulonglong2*)&Ws2[0][cp0 + 4];
        ulonglong2 w3 = *(ulonglong2*)&Ws2[0][cp0 + 6];

#pragma unroll 5
        for (int d = 0; d < DIN - 1; ++d) {
            float na0 = AsR[ra][d + 1];
            float na1 = AsR[rb][d + 1];
            ulonglong2 nw0 = *(ulonglong2*)&Ws2[d + 1][cp0 + 0];
            ulonglong2 nw1 = *(ulonglong2*)&Ws2[d + 1][cp0 + 2];
            ulonglong2 nw2 = *(ulonglong2*)&Ws2[d + 1][cp0 + 4];
            ulonglong2 nw3 = *(ulonglong2*)&Ws2[d + 1][cp0 + 6];
            ull A0 = dup2(a0), A1 = dup2(a1);
            fma2(acc[0][0], A0, w0.x);  fma2(acc[0][1], A0, w0.y);
            fma2(acc[0][2], A0, w1.x);  fma2(acc[0][3], A0, w1.y);
            fma2(acc[0][4], A0, w2.x);  fma2(acc[0][5], A0, w2.y);
            fma2(acc[0][6], A0, w3.x);  fma2(acc[0][7], A0, w3.y);
            fma2(acc[1][0], A1, w0.x);  fma2(acc[1][1], A1, w0.y);
            fma2(acc[1][2], A1, w1.x);  fma2(acc[1][3], A1, w1.y);
            fma2(acc[1][4], A1, w2.x);  fma2(acc[1][5], A1, w2.y);
            fma2(acc[1][6], A1, w3.x);  fma2(acc[1][7], A1, w3.y);
            a0 = na0; a1 = na1; w0 = nw0; w1 = nw1; w2 = nw2; w3 = nw3;
        }
        {   // last d
            ull A0 = dup2(a0), A1 = dup2(a1);
            fma2(acc[0][0], A0, w0.x);  fma2(acc[0][1], A0, w0.y);
            fma2(acc[0][2], A0, w1.x);  fma2(acc[0][3], A0, w1.y);
            fma2(acc[0][4], A0, w2.x);  fma2(acc[0][5], A0, w2.y);
            fma2(acc[0][6], A0, w3.x);  fma2(acc[0][7], A0, w3.y);
            fma2(acc[1][0], A1, w0.x);  fma2(acc[1][1], A1, w0.y);
            fma2(acc[1][2], A1, w1.x);  fma2(acc[1][3], A1, w1.y);
            fma2(acc[1][4], A1, w2.x);  fma2(acc[1][5], A1, w2.y);
            fma2(acc[1][6], A1, w3.x);  fma2(acc[1][7], A1, w3.y);
        }

        // epilogue: rows m0+2L, m0+2L+1; cols 16w..16w+15
        float* outp = g_qkv + (long)(p * H + h) * NBOX * DKD;
#pragma unroll
        for (int i = 0; i < 2; ++i) {
            int row = m0 + ra + i;
#pragma unroll
            for (int t = 0; t < 4; ++t) {
                int col = 16 * w + 4 * t;
                float2 u0 = unpack2(acc[i][2 * t + 0]);
                float2 u1 = unpack2(acc[i][2 * t + 1]);
                float4 b4 = *(const float4*)&bb[h * DKD + col];
                *(float4*)&outp[row * DKD + col] =
                    make_float4(u0.x + b4.x, u0.y + b4.y, u1.x + b4.z, u1.y + b4.w);
            }
        }
    } else {
        // ---------------- gate path ----------------
        float (*pos_s)[65] = (float(*)[65])dsm;              // 64x65 = 16640 B
        float* wg_s = (float*)(dsm + 64 * 65 * 4);           // 16x64 =  4096 B

        int p0 = (blockIdx.x - 96) * 64;   // pair base (pair = m*128+n)

        ((float4*)wg_s)[tid] = ((const float4*)WG)[tid];
#pragma unroll
        for (int it = 0; it < 4; ++it) {
            int fidx = tid + 256 * it;
            int pl = fidx >> 4, g4 = fidx & 15;
            float4 v = ((const float4*)pos)[(long)(p0 + pl) * 16 + g4];
            pos_s[pl][4 * g4 + 0] = v.x;
            pos_s[pl][4 * g4 + 1] = v.y;
            pos_s[pl][4 * g4 + 2] = v.z;
            pos_s[pl][4 * g4 + 3] = v.w;
        }
        __syncthreads();

        int row = tid & 63;
        int hg  = tid >> 6;       // heads {hg, hg+4, hg+8, hg+12}
        float acc[4] = {0.f, 0.f, 0.f, 0.f};
#pragma unroll
        for (int g = 0; g < DG; ++g) {
            float pv = pos_s[row][g];
#pragma unroll
            for (int j = 0; j < 4; ++j)
                acc[j] = fmaf(pv, wg_s[(hg + 4 * j) * DG + g], acc[j]);
        }
#pragma unroll
        for (int j = 0; j < 4; ++j) {
            int h = hg + 4 * j;
            float x = acc[j] + bg[h];
            g_glog[h * (NBOX * NBOX) + p0 + row] = __logf(fmaxf(x, 1e-6f));
        }
    }
}

// ---------------------------------------------------------------------------
// k_attn: 32x128 score tile (f32x2 FMA), + glog, row softmax, partial colsums.
// grid (4, 16), 256 threads.
// ---------------------------------------------------------------------------
__global__ void k_attn() {
    __shared__ __align__(16) ull As2[32][33];
    __shared__ __align__(16) float Bs[32][132];
    __shared__ float psum[8][128];

    int tid = threadIdx.x;
    int mt = blockIdx.x, h = blockIdx.y;
    int m0 = mt * 32;
    int rg = tid >> 5;
    int cg = tid & 31;

    const float* kmat = g_qkv + (long)(0 * H + h) * NBOX * DKD;
    const float* qmat = g_qkv + (long)(1 * H + h) * NBOX * DKD;

    ull acc[4][2] = {};

    for (int kk = 0; kk < DKD; kk += 32) {
        {
            int r = tid >> 3, c4 = tid & 7;
            float4 v = *(const float4*)&kmat[(m0 + r) * DKD + kk + 4 * c4];
            As2[r][4 * c4 + 0] = dup2(v.x);
            As2[r][4 * c4 + 1] = dup2(v.y);
            As2[r][4 * c4 + 2] = dup2(v.z);
            As2[r][4 * c4 + 3] = dup2(v.w);
        }
#pragma unroll
        for (int it = 0; it < 4; ++it) {
            int fidx = tid + 256 * it;
            int n = fidx >> 3, c4 = fidx & 7;
            float4 v = *(const float4*)&qmat[n * DKD + kk + 4 * c4];
            Bs[4 * c4 + 0][n] = v.x;
            Bs[4 * c4 + 1][n] = v.y;
            Bs[4 * c4 + 2][n] = v.z;
            Bs[4 * c4 + 3][n] = v.w;
        }
        __syncthreads();

#pragma unroll
        for (int d = 0; d < 32; ++d) {
            ulonglong2 b = *(ulonglong2*)&Bs[d][4 * cg];
#pragma unroll
            for (int i = 0; i < 4; ++i) {
                ull a = As2[4 * rg + i][d];
                fma2(acc[i][0], a, b.x);
                fma2(acc[i][1], a, b.y);
            }
        }
        __syncthreads();
    }

    const float scale = 0.08838834764831843f;  // 1/sqrt(128)
    float csum[4] = {0.f, 0.f, 0.f, 0.f};
#pragma unroll
    for (int i = 0; i < 4; ++i) {
        int m = m0 + 4 * rg + i;
        float4 gl = *(const float4*)&g_glog[((long)h * NBOX + m) * NBOX + 4 * cg];
        float2 s0 = unpack2(acc[i][0]);
        float2 s1 = unpack2(acc[i][1]);
        float l[4];
        l[0] = s0.x * scale + gl.x;
        l[1] = s0.y * scale + gl.y;
        l[2] = s1.x * scale + gl.z;
        l[3] = s1.y * scale + gl.w;

        float mx = fmaxf(fmaxf(l[0], l[1]), fmaxf(l[2], l[3]));
#pragma unroll
        for (int off = 16; off; off >>= 1)
            mx = fmaxf(mx, __shfl_xor_sync(0xffffffffu, mx, off));

        float e[4], s = 0.f;
#pragma unroll
        for (int j = 0; j < 4; ++j) { e[j] = __expf(l[j] - mx); s += e[j]; }
#pragma unroll
        for (int off = 16; off; off >>= 1)
            s += __shfl_xor_sync(0xffffffffu, s, off);

        float rinv = 1.0f / s;
#pragma unroll
        for (int j = 0; j < 4; ++j) csum[j] += e[j] * rinv;
    }

#pragma unroll
    for (int j = 0; j < 4; ++j) psum[rg][4 * cg + j] = csum[j];
    __syncthreads();

    if (tid < 128) {
        float s = 0.f;
#pragma unroll
        for (int ww = 0; ww < 8; ++ww) s += psum[ww][tid];
        g_partial[(h * 4 + mt) * DKD + tid] = s;
    }
}

// ---------------------------------------------------------------------------
// k_out: out[i, c, d] = v[h,i,k]*colsum[h,k] + f_a[i,d]   (c = h*128+k)
// colsum computed inline from 4 partials. 16.7M float4 streaming stores.
// ---------------------------------------------------------------------------
__global__ void k_out(const float* __restrict__ f_a, float4* __restrict__ out) {
    int idx = blockIdx.x * 512 + threadIdx.x;   // 0..2^24-1
    int d4 = idx & 63;
    int c  = (idx >> 6) & 2047;
    int i  = idx >> 17;
    int h  = c >> 7;
    int k  = c & 127;

    float cs = g_partial[(h * 4 + 0) * DKD + k]
             + g_partial[(h * 4 + 1) * DKD + k]
             + g_partial[(h * 4 + 2) * DKD + k]
             + g_partial[(h * 4 + 3) * DKD + k];
    float s = g_qkv[((long)(2 * H + h) * NBOX + i) * DKD + k] * cs;
    float4 f = ((const float4*)f_a)[i * 64 + d4];
    __stcs(&out[idx], make_float4(s + f.x, s + f.y, s + f.z, s + f.w));
}

// ---------------------------------------------------------------------------
extern "C" void kernel_launch(void* const* d_in, const int* in_sizes, int n_in,
                              void* d_out, int out_size) {
    const float* f_a = (const float*)d_in[0];
    const float* pos = (const float*)d_in[1];
    const float* WG  = (const float*)d_in[2];
    const float* bg  = (const float*)d_in[3];
    const float* WK  = (const float*)d_in[4];
    const float* bk  = (const float*)d_in[5];
    const float* WQ  = (const float*)d_in[6];
    const float* bq  = (const float*)d_in[7];
    const float* WV  = (const float*)d_in[8];
    const float* bv  = (const float*)d_in[9];

    cudaFuncSetAttribute(k_front, cudaFuncAttributeMaxDynamicSharedMemorySize,
                         DS_TOTAL);

    k_front<<<352, 256, DS_TOTAL>>>(f_a, pos, WG, bg, WK, bk, WQ, bq, WV, bv);
    k_attn<<<dim3(4, 16), 256>>>();
    k_out<<<32768, 512>>>(f_a, (float4*)d_out);
}